// round 15
// baseline (speedup 1.0000x reference)
#include <cuda_runtime.h>
#include <cstdint>

#define Bsz 256
#define Tlen 512
#define Iin 5
#define HH 100
#define G4 400
#define NL 5
#define Oout 3
#define BT (Bsz*Tlen)

typedef unsigned long long ull;

#define FMA2(d, a, b, c) asm("fma.rn.f32x2 %0, %1, %2, %3;" : "=l"(d) : "l"(a), "l"(b), "l"(c))
#define ADDF2(d, a, b)   asm("add.rn.f32x2 %0, %1, %2;" : "=l"(d) : "l"(a), "l"(b))
#define PACK2(d, lo, hi) asm("mov.b64 %0, {%1, %2};" : "=l"(d) : "f"(lo), "f"(hi))
#define UNPACK2(lo, hi, v) asm("mov.b64 {%0, %1}, %2;" : "=f"(lo), "=f"(hi) : "l"(v))

// ---------------------------------------------------------------------------
// Scratch.  g_gates uses an INTERLEAVED gate layout: column u*4+s holds the
// pre-activation of gate s (i,f,g,o) of hidden unit u, so the recurrence
// reads 64B-contiguous per warp instead of 13 scattered sectors.
// ---------------------------------------------------------------------------
__device__ float g_gates[(size_t)BT * G4];
__device__ float g_hA[(size_t)BT * HH];
__device__ float g_hB[(size_t)BT * HH];

__device__ __forceinline__ float sigf(float x) {
    return __fdividef(1.0f, 1.0f + __expf(-x));
}
__device__ __forceinline__ float tanh_(float x) {
    return __fdividef(2.0f, 1.0f + __expf(-2.0f * x)) - 1.0f;
}

// gate-row n (= s*100+u) -> interleaved column u*4+s
__device__ __forceinline__ int gperm(int n) {
    int s = n / 100;
    int u = n - s * 100;
    return u * 4 + s;
}

// ---------------------------------------------------------------------------
// Kernel 1a: layer-0 input projection (K=5), permuted store
// ---------------------------------------------------------------------------
__global__ void gemm_in0(const float* __restrict__ x,
                         const float* __restrict__ Wih,
                         const float* __restrict__ bias)
{
    int idx = blockIdx.x * blockDim.x + threadIdx.x;
    int m = idx / G4;
    int n = idx - m * G4;
    const float* xr = x + (size_t)m * Iin;
    const float* wr = Wih + (size_t)n * Iin;
    float a = bias[n];
#pragma unroll
    for (int k = 0; k < Iin; k++) a += xr[k] * wr[k];
    g_gates[(size_t)m * G4 + gperm(n)] = a;
}

// ---------------------------------------------------------------------------
// Kernel 1b: layers 1..4 input projection — round-6 bit-exact core
// (KP=102, float2 loads; verified 344us), epilogue stores permuted column.
// ---------------------------------------------------------------------------
#define GM 64
#define GNJ 7
#define GN (16*GNJ)
#define KP 102
#define GEMM_SMEM ((GM + GN) * KP * 4)

__global__ __launch_bounds__(256)
void gemm_in(int inSel,
             const float* __restrict__ W,
             const float* __restrict__ bias)
{
    extern __shared__ float sm[];
    float* Xs = sm;
    float* Ws = sm + GM * KP;

    const float* X = inSel ? g_hB : g_hA;
    int tid = threadIdx.x;
    int tx = tid & 15;
    int ty = (tid >> 4) & 15;
    size_t m0 = (size_t)blockIdx.x * GM;
    int n0 = blockIdx.y * GN;

    {
        const float2* Xg = (const float2*)(X + m0 * 100);
        for (int idx = tid; idx < GM * 50; idx += 256) {
            int r = idx / 50, c = idx - r * 50;
            float2 v = Xg[(size_t)r * 50 + c];
            *(float2*)&Xs[r * KP + 2 * c] = v;
        }
        const float2* Wg = (const float2*)W;
        for (int idx = tid; idx < GN * 50; idx += 256) {
            int r = idx / 50, c = idx - r * 50;
            int gn = n0 + r;
            float2 v = (gn < G4) ? Wg[(size_t)gn * 50 + c] : make_float2(0.f, 0.f);
            *(float2*)&Ws[r * KP + 2 * c] = v;
        }
    }
    __syncthreads();

    ull acc[4][GNJ];
#pragma unroll
    for (int i = 0; i < 4; i++)
#pragma unroll
        for (int j = 0; j < GNJ; j++) PACK2(acc[i][j], 0.f, 0.f);

    const ull* xrow[4];
#pragma unroll
    for (int i = 0; i < 4; i++) xrow[i] = (const ull*)&Xs[(ty + 16 * i) * KP];
    const ull* wrow[GNJ];
#pragma unroll
    for (int j = 0; j < GNJ; j++) wrow[j] = (const ull*)&Ws[(tx + 16 * j) * KP];

#pragma unroll 5
    for (int k = 0; k < 50; k++) {
        ull dx[4], dw[GNJ];
#pragma unroll
        for (int i = 0; i < 4; i++) dx[i] = xrow[i][k];
#pragma unroll
        for (int j = 0; j < GNJ; j++) dw[j] = wrow[j][k];
#pragma unroll
        for (int i = 0; i < 4; i++)
#pragma unroll
            for (int j = 0; j < GNJ; j++)
                FMA2(acc[i][j], dx[i], dw[j], acc[i][j]);
    }

#pragma unroll
    for (int i = 0; i < 4; i++) {
        size_t m = m0 + ty + 16 * i;
#pragma unroll
        for (int j = 0; j < GNJ; j++) {
            int n = n0 + tx + 16 * j;
            if (n < G4) {
                float lo, hi;
                UNPACK2(lo, hi, acc[i][j]);
                g_gates[m * G4 + gperm(n)] = lo + hi + bias[n];
            }
        }
    }
}

// ---------------------------------------------------------------------------
// Kernel 2: LSTM recurrence — round-10 bit-exact EXCEPT the gate index:
// with interleaved g_gates, lane tid reads column (tid>>1) = u*4+s, so a
// warp's two LDGs hit 2 sectors instead of ~13.
// ---------------------------------------------------------------------------
__global__ __launch_bounds__(800, 1)
void lstm_rec(const float* __restrict__ W_hh,   // [400,100]
              int outSel, int storeAll)
{
    __shared__ __align__(16) float hbuf[2][2][104];  // [parity][row][unit(+pad)]

    const int tid  = threadIdx.x;
    const int u    = tid >> 3;
    const int s    = (tid >> 1) & 3;    // 0=i 1=f 2=g 3=o
    const int half = tid & 1;
    const int grow = s * 100 + u;       // W_hh row (input layout, unchanged)
    const int gidx = tid >> 1;          // interleaved g_gates column (u*4+s)
    const int b0   = blockIdx.x * 2;
    const int lane = tid & 31;
    const int lb   = lane & ~7;
    const int cbase = 13 * half;

    // half of the weight row -> 26 packed regs (chunk 25 = zeros)
    ull w2[26];
    {
        const float4* wr = (const float4*)(W_hh + (size_t)grow * HH);
#pragma unroll
        for (int i = 0; i < 13; i++) {
            int cc = cbase + i;
            float4 v = (cc < 25) ? wr[cc] : make_float4(0.f, 0.f, 0.f, 0.f);
            PACK2(w2[2 * i],     v.x, v.y);
            PACK2(w2[2 * i + 1], v.z, v.w);
        }
    }

    if (tid < 416) ((float*)hbuf)[tid] = 0.f;
    float c = 0.f;                       // live in lanes (tid&7)<2; row = half

    const float* gp0 = g_gates + (size_t)b0 * Tlen * G4 + gidx;
    const float* gp1 = gp0 + (size_t)Tlen * G4;
    float* hout = outSel ? g_hB : g_hA;
    float* hsrow = hout + (size_t)(b0 + half) * Tlen * HH;   // this lane's row

    float pg0 = gp0[0];
    float pg1 = gp1[0];
    __syncthreads();

    for (int t = 0; t < Tlen; t++) {
        const int p = t & 1;
        const float cur0 = (half == 0) ? pg0 : 0.f;   // preact added once/pair
        const float cur1 = (half == 0) ? pg1 : 0.f;

        // dual-row half-dot
        ull a0, a1, e0, e1;
        PACK2(a0, cur0, 0.f); PACK2(a1, 0.f, 0.f);
        PACK2(e0, cur1, 0.f); PACK2(e1, 0.f, 0.f);
        {
            const ulonglong2* hA = (const ulonglong2*)hbuf[p][0];
            const ulonglong2* hB = (const ulonglong2*)hbuf[p][1];
#pragma unroll
            for (int i = 0; i < 13; i++) {
                ulonglong2 vA = hA[cbase + i];
                ulonglong2 vB = hB[cbase + i];
                FMA2(a0, w2[2 * i],     vA.x, a0);
                FMA2(a1, w2[2 * i + 1], vA.y, a1);
                FMA2(e0, w2[2 * i],     vB.x, e0);
                FMA2(e1, w2[2 * i + 1], vB.y, e1);
            }
        }
        // prefetch next step's pre-activations (verified position: after dot,
        // all lanes, unpredicated; now 64B-coalesced per warp)
        {
            int tn = (t + 1 < Tlen) ? (t + 1) : t;
            pg0 = gp0[(size_t)tn * G4];
            pg1 = gp1[(size_t)tn * G4];
        }
        ADDF2(a0, a0, a1);
        ADDF2(e0, e0, e1);
        float q0, q1;
        UNPACK2(q0, q1, a0); float part0 = q0 + q1;
        UNPACK2(q0, q1, e0); float part1 = q0 + q1;

        // combine K halves
        float full0 = part0 + __shfl_xor_sync(0xFFFFFFFFu, part0, 1);
        float full1 = part1 + __shfl_xor_sync(0xFFFFFFFFu, part1, 1);

        // activate ONLY this lane's row (row = half)
        float myfull = half ? full1 : full0;
        float v = (s == 2) ? tanh_(myfull) : sigf(myfull);

        // gather f,g,o for my row (source lanes lb+2/4/6, +half selects row)
        float fv = __shfl_sync(0xFFFFFFFFu, v, lb + 2 + half);
        float gv = __shfl_sync(0xFFFFFFFFu, v, lb + 4 + half);
        float ov = __shfl_sync(0xFFFFFFFFu, v, lb + 6 + half);

        // state update: lane lb -> row0, lane lb+1 -> row1
        const int pn = p ^ 1;
        if ((tid & 7) < 2) {             // s==0; v = my row's input gate
            c = fv * c + v * gv;
            float h = ov * tanh_(c);
            hbuf[pn][half][u] = h;
            if (storeAll || t == Tlen - 1) hsrow[(size_t)t * HH + u] = h;
        }
        __syncthreads();
    }
}

// ---------------------------------------------------------------------------
// Kernel 3: BN + MLP head
// ---------------------------------------------------------------------------
__global__ void head_kernel(int inSel,
                            const float* __restrict__ gamma,
                            const float* __restrict__ beta,
                            const float* __restrict__ rmean,
                            const float* __restrict__ rvar,
                            const float* __restrict__ W1, const float* __restrict__ b1,
                            const float* __restrict__ W2, const float* __restrict__ b2,
                            const float* __restrict__ W3, const float* __restrict__ b3,
                            float* __restrict__ out)
{
    __shared__ float xa[HH], ya[HH];
    const float* hseq = inSel ? g_hB : g_hA;
    int b = blockIdx.x, tid = threadIdx.x;

    if (tid < HH) {
        float v = hseq[((size_t)b * Tlen + (Tlen - 1)) * HH + tid];
        xa[tid] = (v - rmean[tid]) * rsqrtf(rvar[tid] + 1e-5f) * gamma[tid] + beta[tid];
    }
    __syncthreads();
    if (tid < HH) {
        float a = b1[tid];
#pragma unroll 4
        for (int k = 0; k < HH; k++) a += xa[k] * W1[(size_t)tid * HH + k];
        ya[tid] = fmaxf(a, 0.0f);
    }
    __syncthreads();
    if (tid < HH) {
        float a = b2[tid];
#pragma unroll 4
        for (int k = 0; k < HH; k++) a += ya[k] * W2[(size_t)tid * HH + k];
        xa[tid] = fmaxf(a, 0.0f);
    }
    __syncthreads();
    if (tid < Oout) {
        float a = b3[tid];
#pragma unroll 4
        for (int k = 0; k < HH; k++) a += xa[k] * W3[(size_t)tid * HH + k];
        out[(size_t)b * Oout + tid] = a;
    }
}

// ---------------------------------------------------------------------------
// kernel_launch
// ---------------------------------------------------------------------------
extern "C" void kernel_launch(void* const* d_in, const int* in_sizes, int n_in,
                              void* d_out, int out_size)
{
    const float* x     = (const float*)d_in[0];
    const float* W_ih0 = (const float*)d_in[1];
    const float* W_hh0 = (const float*)d_in[2];
    const float* b0    = (const float*)d_in[3];
    const float* W_ih  = (const float*)d_in[4];
    const float* W_hh  = (const float*)d_in[5];
    const float* bb    = (const float*)d_in[6];
    const float* gamma = (const float*)d_in[7];
    const float* beta  = (const float*)d_in[8];
    const float* rmean = (const float*)d_in[9];
    const float* rvar  = (const float*)d_in[10];
    const float* W1    = (const float*)d_in[11];
    const float* b1    = (const float*)d_in[12];
    const float* W2    = (const float*)d_in[13];
    const float* b2    = (const float*)d_in[14];
    const float* W3    = (const float*)d_in[15];
    const float* b3    = (const float*)d_in[16];
    float* out = (float*)d_out;

    static int smem_set = 0;
    if (!smem_set) {
        cudaFuncSetAttribute((const void*)gemm_in,
                             cudaFuncAttributeMaxDynamicSharedMemorySize, GEMM_SMEM);
        smem_set = 1;
    }

    gemm_in0<<<(BT * G4) / 256, 256>>>(x, W_ih0, b0);
    lstm_rec<<<128, 800>>>(W_hh0, 0, 1);

    dim3 ggrid(BT / GM, 4);
    for (int l = 0; l < NL - 1; l++) {
        int inSel  = (l % 2 == 0) ? 0 : 1;
        int outSel = 1 - inSel;
        gemm_in<<<ggrid, 256, GEMM_SMEM>>>(inSel, W_ih + (size_t)l * G4 * HH,
                                           bb + (size_t)l * G4);
        lstm_rec<<<128, 800>>>(W_hh + (size_t)l * G4 * HH, outSel,
                               (l == NL - 2) ? 0 : 1);
    }

    head_kernel<<<Bsz, 128>>>(0, gamma, beta, rmean, rvar,
                              W1, b1, W2, b2, W3, b3, out);
}

// round 16
// speedup vs baseline: 1.0097x; 1.0097x over previous
#include <cuda_runtime.h>
#include <cstdint>

#define Bsz 256
#define Tlen 512
#define Iin 5
#define HH 100
#define G4 400
#define NL 5
#define Oout 3
#define BT (Bsz*Tlen)

typedef unsigned long long ull;

#define FMA2(d, a, b, c) asm("fma.rn.f32x2 %0, %1, %2, %3;" : "=l"(d) : "l"(a), "l"(b), "l"(c))
#define ADDF2(d, a, b)   asm("add.rn.f32x2 %0, %1, %2;" : "=l"(d) : "l"(a), "l"(b))
#define PACK2(d, lo, hi) asm("mov.b64 %0, {%1, %2};" : "=l"(d) : "f"(lo), "f"(hi))
#define UNPACK2(lo, hi, v) asm("mov.b64 {%0, %1}, %2;" : "=f"(lo), "=f"(hi) : "l"(v))

// ---------------------------------------------------------------------------
// Scratch. g_gates is gate-INTERLEAVED: column u*4+s holds gate s of unit u.
// The permutation is applied on the WEIGHT-LOAD side of the gemms (row
// gather is free), so gemm stores stay fully coalesced and the recurrence
// reads 64B-contiguous per warp.
// ---------------------------------------------------------------------------
__device__ float g_gates[(size_t)BT * G4];
__device__ float g_hA[(size_t)BT * HH];
__device__ float g_hB[(size_t)BT * HH];

__device__ __forceinline__ float sigf(float x) {
    return __fdividef(1.0f, 1.0f + __expf(-x));
}
__device__ __forceinline__ float tanh_(float x) {
    return __fdividef(2.0f, 1.0f + __expf(-2.0f * x)) - 1.0f;
}

// interleaved column pn -> original gate row n = (pn&3)*100 + (pn>>2)
__device__ __forceinline__ int ginv(int pn) {
    return (pn & 3) * 100 + (pn >> 2);
}

// ---------------------------------------------------------------------------
// Kernel 1a: layer-0 input projection (K=5). Output column = interleaved pn;
// weight/bias row gathered via ginv. Store fully coalesced.
// ---------------------------------------------------------------------------
__global__ void gemm_in0(const float* __restrict__ x,
                         const float* __restrict__ Wih,
                         const float* __restrict__ bias)
{
    int idx = blockIdx.x * blockDim.x + threadIdx.x;
    int m = idx / G4;
    int pn = idx - m * G4;
    int n = ginv(pn);
    const float* xr = x + (size_t)m * Iin;
    const float* wr = Wih + (size_t)n * Iin;
    float a = bias[n];
#pragma unroll
    for (int k = 0; k < Iin; k++) a += xr[k] * wr[k];
    g_gates[(size_t)idx] = a;
}

// ---------------------------------------------------------------------------
// Kernel 1b: layers 1..4 input projection — round-6 bit-exact core and
// epilogue; ONLY the W/bias row index is permuted at load time.
// ---------------------------------------------------------------------------
#define GM 64
#define GNJ 7
#define GN (16*GNJ)
#define KP 102
#define GEMM_SMEM ((GM + GN) * KP * 4)

__global__ __launch_bounds__(256)
void gemm_in(int inSel,
             const float* __restrict__ W,
             const float* __restrict__ bias)
{
    extern __shared__ float sm[];
    float* Xs = sm;
    float* Ws = sm + GM * KP;

    const float* X = inSel ? g_hB : g_hA;
    int tid = threadIdx.x;
    int tx = tid & 15;
    int ty = (tid >> 4) & 15;
    size_t m0 = (size_t)blockIdx.x * GM;
    int n0 = blockIdx.y * GN;

    {
        const float2* Xg = (const float2*)(X + m0 * 100);
        for (int idx = tid; idx < GM * 50; idx += 256) {
            int r = idx / 50, c = idx - r * 50;
            float2 v = Xg[(size_t)r * 50 + c];
            *(float2*)&Xs[r * KP + 2 * c] = v;
        }
        const float2* Wg = (const float2*)W;
        for (int idx = tid; idx < GN * 50; idx += 256) {
            int r = idx / 50, c = idx - r * 50;
            int pn = n0 + r;
            float2 v = (pn < G4) ? Wg[(size_t)ginv(pn) * 50 + c]
                                 : make_float2(0.f, 0.f);
            *(float2*)&Ws[r * KP + 2 * c] = v;
        }
    }
    __syncthreads();

    ull acc[4][GNJ];
#pragma unroll
    for (int i = 0; i < 4; i++)
#pragma unroll
        for (int j = 0; j < GNJ; j++) PACK2(acc[i][j], 0.f, 0.f);

    const ull* xrow[4];
#pragma unroll
    for (int i = 0; i < 4; i++) xrow[i] = (const ull*)&Xs[(ty + 16 * i) * KP];
    const ull* wrow[GNJ];
#pragma unroll
    for (int j = 0; j < GNJ; j++) wrow[j] = (const ull*)&Ws[(tx + 16 * j) * KP];

#pragma unroll 5
    for (int k = 0; k < 50; k++) {
        ull dx[4], dw[GNJ];
#pragma unroll
        for (int i = 0; i < 4; i++) dx[i] = xrow[i][k];
#pragma unroll
        for (int j = 0; j < GNJ; j++) dw[j] = wrow[j][k];
#pragma unroll
        for (int i = 0; i < 4; i++)
#pragma unroll
            for (int j = 0; j < GNJ; j++)
                FMA2(acc[i][j], dx[i], dw[j], acc[i][j]);
    }

#pragma unroll
    for (int i = 0; i < 4; i++) {
        size_t m = m0 + ty + 16 * i;
#pragma unroll
        for (int j = 0; j < GNJ; j++) {
            int pn = n0 + tx + 16 * j;
            if (pn < G4) {
                float lo, hi;
                UNPACK2(lo, hi, acc[i][j]);
                g_gates[m * G4 + pn] = lo + hi + bias[ginv(pn)];
            }
        }
    }
}

// ---------------------------------------------------------------------------
// Kernel 2: LSTM recurrence — round-15 bit-exact (verified 588us/layer):
// split-K quad-gate, interleaved gate reads (lane tid reads column tid>>1).
// ---------------------------------------------------------------------------
__global__ __launch_bounds__(800, 1)
void lstm_rec(const float* __restrict__ W_hh,   // [400,100]
              int outSel, int storeAll)
{
    __shared__ __align__(16) float hbuf[2][2][104];  // [parity][row][unit(+pad)]

    const int tid  = threadIdx.x;
    const int u    = tid >> 3;
    const int s    = (tid >> 1) & 3;    // 0=i 1=f 2=g 3=o
    const int half = tid & 1;
    const int grow = s * 100 + u;       // W_hh row (input layout, unchanged)
    const int gidx = tid >> 1;          // interleaved g_gates column (u*4+s)
    const int b0   = blockIdx.x * 2;
    const int lane = tid & 31;
    const int lb   = lane & ~7;
    const int cbase = 13 * half;

    // half of the weight row -> 26 packed regs (chunk 25 = zeros)
    ull w2[26];
    {
        const float4* wr = (const float4*)(W_hh + (size_t)grow * HH);
#pragma unroll
        for (int i = 0; i < 13; i++) {
            int cc = cbase + i;
            float4 v = (cc < 25) ? wr[cc] : make_float4(0.f, 0.f, 0.f, 0.f);
            PACK2(w2[2 * i],     v.x, v.y);
            PACK2(w2[2 * i + 1], v.z, v.w);
        }
    }

    if (tid < 416) ((float*)hbuf)[tid] = 0.f;
    float c = 0.f;                       // live in lanes (tid&7)<2; row = half

    const float* gp0 = g_gates + (size_t)b0 * Tlen * G4 + gidx;
    const float* gp1 = gp0 + (size_t)Tlen * G4;
    float* hout = outSel ? g_hB : g_hA;
    float* hsrow = hout + (size_t)(b0 + half) * Tlen * HH;   // this lane's row

    float pg0 = gp0[0];
    float pg1 = gp1[0];
    __syncthreads();

    for (int t = 0; t < Tlen; t++) {
        const int p = t & 1;
        const float cur0 = (half == 0) ? pg0 : 0.f;   // preact added once/pair
        const float cur1 = (half == 0) ? pg1 : 0.f;

        // dual-row half-dot
        ull a0, a1, e0, e1;
        PACK2(a0, cur0, 0.f); PACK2(a1, 0.f, 0.f);
        PACK2(e0, cur1, 0.f); PACK2(e1, 0.f, 0.f);
        {
            const ulonglong2* hA = (const ulonglong2*)hbuf[p][0];
            const ulonglong2* hB = (const ulonglong2*)hbuf[p][1];
#pragma unroll
            for (int i = 0; i < 13; i++) {
                ulonglong2 vA = hA[cbase + i];
                ulonglong2 vB = hB[cbase + i];
                FMA2(a0, w2[2 * i],     vA.x, a0);
                FMA2(a1, w2[2 * i + 1], vA.y, a1);
                FMA2(e0, w2[2 * i],     vB.x, e0);
                FMA2(e1, w2[2 * i + 1], vB.y, e1);
            }
        }
        // prefetch next step's pre-activations (verified: post-dot, all lanes,
        // unpredicated, 64B-coalesced)
        {
            int tn = (t + 1 < Tlen) ? (t + 1) : t;
            pg0 = gp0[(size_t)tn * G4];
            pg1 = gp1[(size_t)tn * G4];
        }
        ADDF2(a0, a0, a1);
        ADDF2(e0, e0, e1);
        float q0, q1;
        UNPACK2(q0, q1, a0); float part0 = q0 + q1;
        UNPACK2(q0, q1, e0); float part1 = q0 + q1;

        // combine K halves
        float full0 = part0 + __shfl_xor_sync(0xFFFFFFFFu, part0, 1);
        float full1 = part1 + __shfl_xor_sync(0xFFFFFFFFu, part1, 1);

        // activate ONLY this lane's row (row = half)
        float myfull = half ? full1 : full0;
        float v = (s == 2) ? tanh_(myfull) : sigf(myfull);

        // gather f,g,o for my row (source lanes lb+2/4/6, +half selects row)
        float fv = __shfl_sync(0xFFFFFFFFu, v, lb + 2 + half);
        float gv = __shfl_sync(0xFFFFFFFFu, v, lb + 4 + half);
        float ov = __shfl_sync(0xFFFFFFFFu, v, lb + 6 + half);

        // state update: lane lb -> row0, lane lb+1 -> row1
        const int pn = p ^ 1;
        if ((tid & 7) < 2) {             // s==0; v = my row's input gate
            c = fv * c + v * gv;
            float h = ov * tanh_(c);
            hbuf[pn][half][u] = h;
            if (storeAll || t == Tlen - 1) hsrow[(size_t)t * HH + u] = h;
        }
        __syncthreads();
    }
}

// ---------------------------------------------------------------------------
// Kernel 3: BN + MLP head
// ---------------------------------------------------------------------------
__global__ void head_kernel(int inSel,
                            const float* __restrict__ gamma,
                            const float* __restrict__ beta,
                            const float* __restrict__ rmean,
                            const float* __restrict__ rvar,
                            const float* __restrict__ W1, const float* __restrict__ b1,
                            const float* __restrict__ W2, const float* __restrict__ b2,
                            const float* __restrict__ W3, const float* __restrict__ b3,
                            float* __restrict__ out)
{
    __shared__ float xa[HH], ya[HH];
    const float* hseq = inSel ? g_hB : g_hA;
    int b = blockIdx.x, tid = threadIdx.x;

    if (tid < HH) {
        float v = hseq[((size_t)b * Tlen + (Tlen - 1)) * HH + tid];
        xa[tid] = (v - rmean[tid]) * rsqrtf(rvar[tid] + 1e-5f) * gamma[tid] + beta[tid];
    }
    __syncthreads();
    if (tid < HH) {
        float a = b1[tid];
#pragma unroll 4
        for (int k = 0; k < HH; k++) a += xa[k] * W1[(size_t)tid * HH + k];
        ya[tid] = fmaxf(a, 0.0f);
    }
    __syncthreads();
    if (tid < HH) {
        float a = b2[tid];
#pragma unroll 4
        for (int k = 0; k < HH; k++) a += ya[k] * W2[(size_t)tid * HH + k];
        xa[tid] = fmaxf(a, 0.0f);
    }
    __syncthreads();
    if (tid < Oout) {
        float a = b3[tid];
#pragma unroll 4
        for (int k = 0; k < HH; k++) a += xa[k] * W3[(size_t)tid * HH + k];
        out[(size_t)b * Oout + tid] = a;
    }
}

// ---------------------------------------------------------------------------
// kernel_launch
// ---------------------------------------------------------------------------
extern "C" void kernel_launch(void* const* d_in, const int* in_sizes, int n_in,
                              void* d_out, int out_size)
{
    const float* x     = (const float*)d_in[0];
    const float* W_ih0 = (const float*)d_in[1];
    const float* W_hh0 = (const float*)d_in[2];
    const float* b0    = (const float*)d_in[3];
    const float* W_ih  = (const float*)d_in[4];
    const float* W_hh  = (const float*)d_in[5];
    const float* bb    = (const float*)d_in[6];
    const float* gamma = (const float*)d_in[7];
    const float* beta  = (const float*)d_in[8];
    const float* rmean = (const float*)d_in[9];
    const float* rvar  = (const float*)d_in[10];
    const float* W1    = (const float*)d_in[11];
    const float* b1    = (const float*)d_in[12];
    const float* W2    = (const float*)d_in[13];
    const float* b2    = (const float*)d_in[14];
    const float* W3    = (const float*)d_in[15];
    const float* b3    = (const float*)d_in[16];
    float* out = (float*)d_out;

    static int smem_set = 0;
    if (!smem_set) {
        cudaFuncSetAttribute((const void*)gemm_in,
                             cudaFuncAttributeMaxDynamicSharedMemorySize, GEMM_SMEM);
        smem_set = 1;
    }

    gemm_in0<<<(BT * G4) / 256, 256>>>(x, W_ih0, b0);
    lstm_rec<<<128, 800>>>(W_hh0, 0, 1);

    dim3 ggrid(BT / GM, 4);
    for (int l = 0; l < NL - 1; l++) {
        int inSel  = (l % 2 == 0) ? 0 : 1;
        int outSel = 1 - inSel;
        gemm_in<<<ggrid, 256, GEMM_SMEM>>>(inSel, W_ih + (size_t)l * G4 * HH,
                                           bb + (size_t)l * G4);
        lstm_rec<<<128, 800>>>(W_hh + (size_t)l * G4 * HH, outSel,
                               (l == NL - 2) ? 0 : 1);
    }

    head_kernel<<<Bsz, 128>>>(0, gamma, beta, rmean, rvar,
                              W1, b1, W2, b2, W3, b3, out);
}

// round 17
// speedup vs baseline: 1.0681x; 1.0578x over previous
#include <cuda_runtime.h>
#include <cstdint>

#define Bsz 256
#define Tlen 512
#define Iin 5
#define HH 100
#define G4 400
#define NL 5
#define Oout 3
#define BT (Bsz*Tlen)

typedef unsigned long long ull;

#define FMA2(d, a, b, c) asm("fma.rn.f32x2 %0, %1, %2, %3;" : "=l"(d) : "l"(a), "l"(b), "l"(c))
#define ADDF2(d, a, b)   asm("add.rn.f32x2 %0, %1, %2;" : "=l"(d) : "l"(a), "l"(b))
#define PACK2(d, lo, hi) asm("mov.b64 %0, {%1, %2};" : "=l"(d) : "f"(lo), "f"(hi))
#define UNPACK2(lo, hi, v) asm("mov.b64 {%0, %1}, %2;" : "=f"(lo), "=f"(hi) : "l"(v))

// tf32 split: hi = rna(x), lo = rna(x - hi)  (3xTF32 -> ~fp32 accuracy)
#define TF32CVT(d, x) asm("cvt.rna.tf32.f32 %0, %1;" : "=r"(d) : "f"(x))

#define MMA_TF32(c0, c1, c2, c3, a0, a1, a2, a3, b0, b1) \
    asm("mma.sync.aligned.m16n8k8.row.col.f32.tf32.tf32.f32 " \
        "{%0,%1,%2,%3},{%4,%5,%6,%7},{%8,%9},{%0,%1,%2,%3};" \
        : "+f"(c0), "+f"(c1), "+f"(c2), "+f"(c3) \
        : "r"(a0), "r"(a1), "r"(a2), "r"(a3), "r"(b0), "r"(b1))

// ---------------------------------------------------------------------------
// Scratch (native gate layout: column n = s*100+u)
// ---------------------------------------------------------------------------
__device__ float g_gates[(size_t)BT * G4];
__device__ float g_hA[(size_t)BT * HH];
__device__ float g_hB[(size_t)BT * HH];

__device__ __forceinline__ float sigf(float x) {
    return __fdividef(1.0f, 1.0f + __expf(-x));
}
__device__ __forceinline__ float tanh_(float x) {
    return __fdividef(2.0f, 1.0f + __expf(-2.0f * x)) - 1.0f;
}

// ---------------------------------------------------------------------------
// Kernel 1a: layer-0 input projection (K=5) — round-10 exact
// ---------------------------------------------------------------------------
__global__ void gemm_in0(const float* __restrict__ x,
                         const float* __restrict__ Wih,
                         const float* __restrict__ bias)
{
    int idx = blockIdx.x * blockDim.x + threadIdx.x;
    int m = idx / G4;
    int n = idx - m * G4;
    const float* xr = x + (size_t)m * Iin;
    const float* wr = Wih + (size_t)n * Iin;
    float a = bias[n];
#pragma unroll
    for (int k = 0; k < Iin; k++) a += xr[k] * wr[k];
    g_gates[(size_t)idx] = a;
}

// ---------------------------------------------------------------------------
// Kernel 1b: layers 1..4 input projection — TENSOR CORE (tf32 3x split).
//   C[BT,400] = X[BT,100] @ W[400,100]^T + bias
// Block: 256 thr (8 warps), tile M=128 x N=64, K padded 100->104 (13 steps).
// Warp w owns m-rows [16w,16w+16); 8 n-subtiles of 8. Smem row stride 108
// (12*g mod 32 distinct -> conflict-free fragment loads).
// ---------------------------------------------------------------------------
#define TM 128
#define TN 64
#define TSTR 108
#define TC_SMEM ((TM + TN) * TSTR * 4)   // 82944 B -> 2 blocks/SM

__global__ __launch_bounds__(256)
void gemm_tc(int inSel,
             const float* __restrict__ W,      // [400,100]
             const float* __restrict__ bias)   // [400]
{
    extern __shared__ float sm[];
    float* Xs = sm;                 // [128][108], cols 100..103 zero
    float* Ws = sm + TM * TSTR;     // [64][108],  cols 100..103 zero

    const float* X = inSel ? g_hB : g_hA;
    int tid = threadIdx.x;
    size_t m0 = (size_t)blockIdx.x * TM;
    int n0 = blockIdx.y * TN;

    // Fill tiles (26 float4 per row; element 25 = zero pad for k 100..103)
    {
        const float4* Xg = (const float4*)(X + m0 * 100);
        for (int i = tid; i < TM * 26; i += 256) {
            int r = i / 26, c = i - r * 26;
            float4 v = (c < 25) ? Xg[(size_t)r * 25 + c]
                                : make_float4(0.f, 0.f, 0.f, 0.f);
            *(float4*)&Xs[r * TSTR + 4 * c] = v;
        }
        const float4* Wg = (const float4*)W;
        for (int i = tid; i < TN * 26; i += 256) {
            int r = i / 26, c = i - r * 26;
            int gn = n0 + r;
            float4 v = (c < 25 && gn < G4) ? Wg[(size_t)gn * 25 + c]
                                           : make_float4(0.f, 0.f, 0.f, 0.f);
            *(float4*)&Ws[r * TSTR + 4 * c] = v;
        }
    }
    __syncthreads();

    const int warp = tid >> 5, lane = tid & 31;
    const int g = lane >> 2, tg = lane & 3;
    const int mrow = warp * 16;

    float acc[8][4];
#pragma unroll
    for (int ns = 0; ns < 8; ns++)
#pragma unroll
        for (int q = 0; q < 4; q++) acc[ns][q] = 0.f;

    const float* Xr0 = &Xs[(mrow + g) * TSTR];
    const float* Xr1 = &Xs[(mrow + g + 8) * TSTR];
    const float* Wr  = &Ws[g * TSTR];

    for (int ks = 0; ks < 13; ks++) {
        const int k0 = ks * 8;
        // A fragments (m16n8k8 row-major): a0=(g,tg) a1=(g+8,tg) a2=(g,tg+4) a3=(g+8,tg+4)
        float fa0 = Xr0[k0 + tg];
        float fa1 = Xr1[k0 + tg];
        float fa2 = Xr0[k0 + tg + 4];
        float fa3 = Xr1[k0 + tg + 4];
        uint32_t ah[4], al[4];
        {
            float f[4] = {fa0, fa1, fa2, fa3};
#pragma unroll
            for (int q = 0; q < 4; q++) {
                TF32CVT(ah[q], f[q]);
                float r = f[q] - __uint_as_float(ah[q]);
                TF32CVT(al[q], r);
            }
        }
#pragma unroll
        for (int ns = 0; ns < 8; ns++) {
            // B fragments (col-major k x n): b0=(k=tg, n=g) b1=(k=tg+4, n=g)
            float fb0 = Wr[ns * 8 * TSTR + k0 + tg];
            float fb1 = Wr[ns * 8 * TSTR + k0 + tg + 4];
            uint32_t bh0, bh1, bl0, bl1;
            TF32CVT(bh0, fb0);
            TF32CVT(bh1, fb1);
            float r0 = fb0 - __uint_as_float(bh0);
            float r1 = fb1 - __uint_as_float(bh1);
            TF32CVT(bl0, r0);
            TF32CVT(bl1, r1);
            // 3xTF32: ah*bh + al*bh + ah*bl
            MMA_TF32(acc[ns][0], acc[ns][1], acc[ns][2], acc[ns][3],
                     ah[0], ah[1], ah[2], ah[3], bh0, bh1);
            MMA_TF32(acc[ns][0], acc[ns][1], acc[ns][2], acc[ns][3],
                     al[0], al[1], al[2], al[3], bh0, bh1);
            MMA_TF32(acc[ns][0], acc[ns][1], acc[ns][2], acc[ns][3],
                     ah[0], ah[1], ah[2], ah[3], bl0, bl1);
        }
    }

    // Epilogue: C fragment (g, 2tg) / (g+8, 2tg); paired-n float2 stores
    size_t mA = m0 + mrow + g;
#pragma unroll
    for (int ns = 0; ns < 8; ns++) {
        int n = n0 + ns * 8 + 2 * tg;
        if (n < G4) {
            float2 v0 = make_float2(acc[ns][0] + bias[n], acc[ns][1] + bias[n + 1]);
            float2 v1 = make_float2(acc[ns][2] + bias[n], acc[ns][3] + bias[n + 1]);
            *(float2*)&g_gates[mA * G4 + n] = v0;
            *(float2*)&g_gates[(mA + 8) * G4 + n] = v1;
        }
    }
}

// ---------------------------------------------------------------------------
// Kernel 2: LSTM recurrence — round-10 BIT-EXACT (verified 596us/layer)
// ---------------------------------------------------------------------------
__global__ __launch_bounds__(800, 1)
void lstm_rec(const float* __restrict__ W_hh,   // [400,100]
              int outSel, int storeAll)
{
    __shared__ __align__(16) float hbuf[2][2][104];

    const int tid  = threadIdx.x;
    const int u    = tid >> 3;
    const int s    = (tid >> 1) & 3;
    const int half = tid & 1;
    const int grow = s * 100 + u;
    const int b0   = blockIdx.x * 2;
    const int lane = tid & 31;
    const int lb   = lane & ~7;
    const int cbase = 13 * half;

    ull w2[26];
    {
        const float4* wr = (const float4*)(W_hh + (size_t)grow * HH);
#pragma unroll
        for (int i = 0; i < 13; i++) {
            int cc = cbase + i;
            float4 v = (cc < 25) ? wr[cc] : make_float4(0.f, 0.f, 0.f, 0.f);
            PACK2(w2[2 * i],     v.x, v.y);
            PACK2(w2[2 * i + 1], v.z, v.w);
        }
    }

    if (tid < 416) ((float*)hbuf)[tid] = 0.f;
    float c = 0.f;

    const float* gp0 = g_gates + (size_t)b0 * Tlen * G4;
    const float* gp1 = gp0 + (size_t)Tlen * G4;
    float* hout = outSel ? g_hB : g_hA;
    float* hsrow = hout + (size_t)(b0 + half) * Tlen * HH;

    float pg0 = gp0[grow];
    float pg1 = gp1[grow];
    __syncthreads();

    for (int t = 0; t < Tlen; t++) {
        const int p = t & 1;
        const float cur0 = (half == 0) ? pg0 : 0.f;
        const float cur1 = (half == 0) ? pg1 : 0.f;

        ull a0, a1, e0, e1;
        PACK2(a0, cur0, 0.f); PACK2(a1, 0.f, 0.f);
        PACK2(e0, cur1, 0.f); PACK2(e1, 0.f, 0.f);
        {
            const ulonglong2* hA = (const ulonglong2*)hbuf[p][0];
            const ulonglong2* hB = (const ulonglong2*)hbuf[p][1];
#pragma unroll
            for (int i = 0; i < 13; i++) {
                ulonglong2 vA = hA[cbase + i];
                ulonglong2 vB = hB[cbase + i];
                FMA2(a0, w2[2 * i],     vA.x, a0);
                FMA2(a1, w2[2 * i + 1], vA.y, a1);
                FMA2(e0, w2[2 * i],     vB.x, e0);
                FMA2(e1, w2[2 * i + 1], vB.y, e1);
            }
        }
        {
            int tn = (t + 1 < Tlen) ? (t + 1) : t;
            pg0 = gp0[(size_t)tn * G4 + grow];
            pg1 = gp1[(size_t)tn * G4 + grow];
        }
        ADDF2(a0, a0, a1);
        ADDF2(e0, e0, e1);
        float q0, q1;
        UNPACK2(q0, q1, a0); float part0 = q0 + q1;
        UNPACK2(q0, q1, e0); float part1 = q0 + q1;

        float full0 = part0 + __shfl_xor_sync(0xFFFFFFFFu, part0, 1);
        float full1 = part1 + __shfl_xor_sync(0xFFFFFFFFu, part1, 1);

        float myfull = half ? full1 : full0;
        float v = (s == 2) ? tanh_(myfull) : sigf(myfull);

        float fv = __shfl_sync(0xFFFFFFFFu, v, lb + 2 + half);
        float gv = __shfl_sync(0xFFFFFFFFu, v, lb + 4 + half);
        float ov = __shfl_sync(0xFFFFFFFFu, v, lb + 6 + half);

        const int pn = p ^ 1;
        if ((tid & 7) < 2) {
            c = fv * c + v * gv;
            float h = ov * tanh_(c);
            hbuf[pn][half][u] = h;
            if (storeAll || t == Tlen - 1) hsrow[(size_t)t * HH + u] = h;
        }
        __syncthreads();
    }
}

// ---------------------------------------------------------------------------
// Kernel 3: BN + MLP head — round-10 exact
// ---------------------------------------------------------------------------
__global__ void head_kernel(int inSel,
                            const float* __restrict__ gamma,
                            const float* __restrict__ beta,
                            const float* __restrict__ rmean,
                            const float* __restrict__ rvar,
                            const float* __restrict__ W1, const float* __restrict__ b1,
                            const float* __restrict__ W2, const float* __restrict__ b2,
                            const float* __restrict__ W3, const float* __restrict__ b3,
                            float* __restrict__ out)
{
    __shared__ float xa[HH], ya[HH];
    const float* hseq = inSel ? g_hB : g_hA;
    int b = blockIdx.x, tid = threadIdx.x;

    if (tid < HH) {
        float v = hseq[((size_t)b * Tlen + (Tlen - 1)) * HH + tid];
        xa[tid] = (v - rmean[tid]) * rsqrtf(rvar[tid] + 1e-5f) * gamma[tid] + beta[tid];
    }
    __syncthreads();
    if (tid < HH) {
        float a = b1[tid];
#pragma unroll 4
        for (int k = 0; k < HH; k++) a += xa[k] * W1[(size_t)tid * HH + k];
        ya[tid] = fmaxf(a, 0.0f);
    }
    __syncthreads();
    if (tid < HH) {
        float a = b2[tid];
#pragma unroll 4
        for (int k = 0; k < HH; k++) a += ya[k] * W2[(size_t)tid * HH + k];
        xa[tid] = fmaxf(a, 0.0f);
    }
    __syncthreads();
    if (tid < Oout) {
        float a = b3[tid];
#pragma unroll 4
        for (int k = 0; k < HH; k++) a += xa[k] * W3[(size_t)tid * HH + k];
        out[(size_t)b * Oout + tid] = a;
    }
}

// ---------------------------------------------------------------------------
// kernel_launch
// ---------------------------------------------------------------------------
extern "C" void kernel_launch(void* const* d_in, const int* in_sizes, int n_in,
                              void* d_out, int out_size)
{
    const float* x     = (const float*)d_in[0];
    const float* W_ih0 = (const float*)d_in[1];
    const float* W_hh0 = (const float*)d_in[2];
    const float* b0    = (const float*)d_in[3];
    const float* W_ih  = (const float*)d_in[4];
    const float* W_hh  = (const float*)d_in[5];
    const float* bb    = (const float*)d_in[6];
    const float* gamma = (const float*)d_in[7];
    const float* beta  = (const float*)d_in[8];
    const float* rmean = (const float*)d_in[9];
    const float* rvar  = (const float*)d_in[10];
    const float* W1    = (const float*)d_in[11];
    const float* b1    = (const float*)d_in[12];
    const float* W2    = (const float*)d_in[13];
    const float* b2    = (const float*)d_in[14];
    const float* W3    = (const float*)d_in[15];
    const float* b3    = (const float*)d_in[16];
    float* out = (float*)d_out;

    static int smem_set = 0;
    if (!smem_set) {
        cudaFuncSetAttribute((const void*)gemm_tc,
                             cudaFuncAttributeMaxDynamicSharedMemorySize, TC_SMEM);
        smem_set = 1;
    }

    gemm_in0<<<(BT * G4) / 256, 256>>>(x, W_ih0, b0);
    lstm_rec<<<128, 800>>>(W_hh0, 0, 1);

    dim3 tgrid(BT / TM, (G4 + TN - 1) / TN);   // 1024 x 7
    for (int l = 0; l < NL - 1; l++) {
        int inSel  = (l % 2 == 0) ? 0 : 1;
        int outSel = 1 - inSel;
        gemm_tc<<<tgrid, 256, TC_SMEM>>>(inSel, W_ih + (size_t)l * G4 * HH,
                                         bb + (size_t)l * G4);
        lstm_rec<<<128, 800>>>(W_hh + (size_t)l * G4 * HH, outSel,
                               (l == NL - 2) ? 0 : 1);
    }

    head_kernel<<<Bsz, 128>>>(0, gamma, beta, rmean, rvar,
                              W1, b1, W2, b2, W3, b3, out);
}